// round 1
// baseline (speedup 1.0000x reference)
#include <cuda_runtime.h>
#include <math.h>

// Problem constants
#define S_LEN 4096
#define BATCH 16
#define H2DIM 1024
#define NCHUNK 152                       // one CTA per SM (GB300: 152 SMs)
#define CHUNK ((S_LEN + NCHUNK - 1) / NCHUNK)   // 27

// Scratch (allocation-free contract: __device__ globals)
__device__ float g_altered[BATCH * H2DIM];             // state @ attn_w^T + b
__device__ float g_wraw[BATCH * S_LEN];                // raw logits
__device__ float g_m[NCHUNK * BATCH];                  // per-chunk running max
__device__ float g_l[NCHUNK * BATCH];                  // per-chunk running sum
__device__ float g_acc[(size_t)NCHUNK * BATCH * H2DIM]; // per-chunk weighted sums (~10MB)

// ---------------------------------------------------------------------------
// Kernel 1: altered_state[b,i] = sum_j state[b,j]*attn_w[i,j] + attn_b[i]
// grid = H2DIM blocks (one output column i), 512 threads = 16 warps (warp b).
// ---------------------------------------------------------------------------
__global__ void __launch_bounds__(512, 2)
k_altered(const float* __restrict__ state,
          const float* __restrict__ attn_w,
          const float* __restrict__ attn_b)
{
    const int i = blockIdx.x;
    __shared__ float wrow[H2DIM];
    // Stage attn_w row i (4KB) into smem, float4 coalesced.
    const float4* wsrc = (const float4*)(attn_w + (size_t)i * H2DIM);
    for (int j = threadIdx.x; j < H2DIM / 4; j += 512)
        ((float4*)wrow)[j] = wsrc[j];
    __syncthreads();

    const int b = threadIdx.x >> 5;
    const int lane = threadIdx.x & 31;
    const float* st = state + b * H2DIM;
    float sum = 0.f;
#pragma unroll 8
    for (int k = 0; k < 32; k++) {
        int j = lane + 32 * k;
        sum = fmaf(wrow[j], __ldg(st + j), sum);
    }
#pragma unroll
    for (int off = 16; off > 0; off >>= 1)
        sum += __shfl_xor_sync(0xffffffffu, sum, off);
    if (lane == 0)
        g_altered[b * H2DIM + i] = sum + attn_b[i];
}

// ---------------------------------------------------------------------------
// Kernel 2: single-pass online softmax over a chunk of S, per batch.
// grid = NCHUNK, block = 512 (warp b owns batch b). No block syncs in mainloop.
// Each lane owns 32 of the 1024 hidden dims: d = 4*lane + 128*k (+0..3).
// ---------------------------------------------------------------------------
__global__ void __launch_bounds__(512, 1)
k_mainpass(const float* __restrict__ enc)
{
    const int b = threadIdx.x >> 5;
    const int lane = threadIdx.x & 31;
    const int c = blockIdx.x;
    const int s0 = c * CHUNK;
    const int s1 = min(s0 + CHUNK, S_LEN);

    // Load my slice of altered_state[b,:] into registers.
    float alt[32];
    {
        const float4* ap = (const float4*)(g_altered + b * H2DIM);
#pragma unroll
        for (int k = 0; k < 8; k++) {
            float4 v = ap[lane + 32 * k];
            alt[4 * k + 0] = v.x; alt[4 * k + 1] = v.y;
            alt[4 * k + 2] = v.z; alt[4 * k + 3] = v.w;
        }
    }

    float acc[32];
#pragma unroll
    for (int j = 0; j < 32; j++) acc[j] = 0.f;
    float m = -1e30f;
    float l = 0.f;

    for (int s = s0; s < s1; s++) {
        const float4* row = (const float4*)(enc + ((size_t)s * BATCH + b) * H2DIM);
        float4 e[8];
#pragma unroll
        for (int k = 0; k < 8; k++) e[k] = __ldg(row + lane + 32 * k);

        // logit fragment
        float w = 0.f;
#pragma unroll
        for (int k = 0; k < 8; k++) {
            w = fmaf(e[k].x, alt[4 * k + 0], w);
            w = fmaf(e[k].y, alt[4 * k + 1], w);
            w = fmaf(e[k].z, alt[4 * k + 2], w);
            w = fmaf(e[k].w, alt[4 * k + 3], w);
        }
#pragma unroll
        for (int off = 16; off > 0; off >>= 1)
            w += __shfl_xor_sync(0xffffffffu, w, off);

        // online softmax update (warp-uniform branch)
        if (w > m) {
            float sc = __expf(m - w);      // first iter: exp(-huge) = 0
            m = w;
            l *= sc;
#pragma unroll
            for (int j = 0; j < 32; j++) acc[j] *= sc;
        }
        float p = __expf(w - m);
        l += p;
#pragma unroll
        for (int k = 0; k < 8; k++) {
            acc[4 * k + 0] = fmaf(p, e[k].x, acc[4 * k + 0]);
            acc[4 * k + 1] = fmaf(p, e[k].y, acc[4 * k + 1]);
            acc[4 * k + 2] = fmaf(p, e[k].z, acc[4 * k + 2]);
            acc[4 * k + 3] = fmaf(p, e[k].w, acc[4 * k + 3]);
        }
        if (lane == 0) g_wraw[b * S_LEN + s] = w;
    }

    if (lane == 0) {
        g_m[c * BATCH + b] = m;
        g_l[c * BATCH + b] = l;
    }
    float4* outp = (float4*)(g_acc + ((size_t)c * BATCH + b) * H2DIM);
#pragma unroll
    for (int k = 0; k < 8; k++)
        outp[lane + 32 * k] = make_float4(acc[4 * k + 0], acc[4 * k + 1],
                                          acc[4 * k + 2], acc[4 * k + 3]);
}

// ---------------------------------------------------------------------------
// Kernel 3: per-batch merge of chunk partials + write both outputs.
// out layout: [0 : B*H2) attention_applied, [B*H2 : B*H2 + B*S) normalized_weights
// grid = BATCH, block = 1024.
// ---------------------------------------------------------------------------
__global__ void __launch_bounds__(1024, 1)
k_combine(float* __restrict__ out)
{
    const int b = blockIdx.x;
    const int tid = threadIdx.x;
    __shared__ float s_coef[NCHUNK];
    __shared__ float s_M, s_L;

    if (tid < 32) {
        float mx = -1e30f;
        for (int c = tid; c < NCHUNK; c += 32)
            mx = fmaxf(mx, g_m[c * BATCH + b]);
#pragma unroll
        for (int off = 16; off > 0; off >>= 1)
            mx = fmaxf(mx, __shfl_xor_sync(0xffffffffu, mx, off));
        float ls = 0.f;
        for (int c = tid; c < NCHUNK; c += 32)
            ls += __expf(g_m[c * BATCH + b] - mx) * g_l[c * BATCH + b];
#pragma unroll
        for (int off = 16; off > 0; off >>= 1)
            ls += __shfl_xor_sync(0xffffffffu, ls, off);
        if (tid == 0) { s_M = mx; s_L = ls; }
    }
    __syncthreads();
    const float M = s_M;
    const float invL = 1.f / s_L;
    if (tid < NCHUNK) s_coef[tid] = __expf(g_m[tid * BATCH + b] - M);
    __syncthreads();

    // attention_applied[b, d]
    {
        const int d = tid;  // 1024 threads == H2DIM
        float a = 0.f;
#pragma unroll 4
        for (int c = 0; c < NCHUNK; c++)
            a = fmaf(s_coef[c], g_acc[((size_t)c * BATCH + b) * H2DIM + d], a);
        out[b * H2DIM + d] = a * invL;
    }
    // normalized_weights[b, s]
    float* out2 = out + BATCH * H2DIM;
#pragma unroll
    for (int s = tid; s < S_LEN; s += 1024)
        out2[b * S_LEN + s] = __expf(g_wraw[b * S_LEN + s] - M) * invL;
}

// ---------------------------------------------------------------------------
// Launch. Input order (metadata): encoder_outputs, state, previous_attention,
// attn_w, attn_b, time_w, time_b. time branch is dead -> never touched.
// ---------------------------------------------------------------------------
extern "C" void kernel_launch(void* const* d_in, const int* in_sizes, int n_in,
                              void* d_out, int out_size)
{
    const float* enc    = (const float*)d_in[0];
    const float* state  = (const float*)d_in[1];
    const float* attn_w = (const float*)d_in[3];
    const float* attn_b = (const float*)d_in[4];
    float* out = (float*)d_out;

    k_altered<<<H2DIM, 512>>>(state, attn_w, attn_b);
    k_mainpass<<<NCHUNK, 512>>>(enc);
    k_combine<<<BATCH, 1024>>>(out);
}

// round 2
// speedup vs baseline: 1.0349x; 1.0349x over previous
#include <cuda_runtime.h>
#include <math.h>

#define S_LEN 4096
#define BATCH 16
#define H2DIM 1024
#define NCHUNK 152
#define CHUNK ((S_LEN + NCHUNK - 1) / NCHUNK)   // 27
#define STAGE_BYTES 65536                        // one s-row: 16*1024*4
#define NSTAGE 3

// Scratch (allocation-free contract)
__device__ float g_altered[BATCH * H2DIM];
__device__ float g_wraw[BATCH * S_LEN];
__device__ float g_m[NCHUNK * BATCH];
__device__ float g_l[NCHUNK * BATCH];
__device__ float g_acc[(size_t)NCHUNK * BATCH * H2DIM];

// ---------------------------------------------------------------------------
// Kernel 1: altered_state = state @ attn_w^T + attn_b
// grid=152, block=512. State staged once in smem; warp gw handles row
// r = wid*152 + blockIdx.x (each of the 1024 rows handled by exactly one warp).
// ---------------------------------------------------------------------------
__global__ void __launch_bounds__(512, 1)
k_altered(const float* __restrict__ state,
          const float* __restrict__ attn_w,
          const float* __restrict__ attn_b)
{
    extern __shared__ float s_state[];            // 16384 floats = 64KB
    const int tid = threadIdx.x;

    float4* sv = (float4*)s_state;
    const float4* gs = (const float4*)state;
#pragma unroll
    for (int k = 0; k < 8; k++) sv[tid + 512 * k] = __ldg(gs + tid + 512 * k);
    __syncthreads();

    const int wid = tid >> 5, lane = tid & 31;
    const int r = wid * 152 + blockIdx.x;
    if (r >= H2DIM) return;

    const float4* wr = (const float4*)(attn_w + (size_t)r * H2DIM);
    float4 wv[8];
#pragma unroll
    for (int k = 0; k < 8; k++) wv[k] = __ldg(wr + lane + 32 * k);
    const float bias = __ldg(attn_b + r);

    float res[BATCH];
#pragma unroll
    for (int b = 0; b < BATCH; b++) {
        const float4* st = (const float4*)(s_state + b * H2DIM);
        float p = 0.f;
#pragma unroll
        for (int k = 0; k < 8; k++) {
            float4 s4 = st[lane + 32 * k];
            p = fmaf(wv[k].x, s4.x, p);
            p = fmaf(wv[k].y, s4.y, p);
            p = fmaf(wv[k].z, s4.z, p);
            p = fmaf(wv[k].w, s4.w, p);
        }
#pragma unroll
        for (int off = 16; off > 0; off >>= 1)
            p += __shfl_xor_sync(0xffffffffu, p, off);
        res[b] = p;
    }
    if (lane < BATCH)
        g_altered[lane * H2DIM + r] = res[lane] + bias;
}

// ---------------------------------------------------------------------------
// Kernel 2: single-pass online softmax, cp.async 3-stage smem pipeline.
// grid=152, block=512, warp b owns batch b. Dynamic smem = 3 * 64KB.
// ---------------------------------------------------------------------------
__device__ __forceinline__ void issue_stage(char* sbuf, const float* gsrc, int tid)
{
    unsigned saddr = (unsigned)__cvta_generic_to_shared(sbuf) + tid * 16;
    const char* g = (const char*)gsrc + tid * 16;
#pragma unroll
    for (int r = 0; r < 8; r++) {
        asm volatile("cp.async.cg.shared.global [%0], [%1], 16;\n"
                     :: "r"(saddr + r * 8192), "l"(g + r * 8192));
    }
}

__global__ void __launch_bounds__(512, 1)
k_mainpass(const float* __restrict__ enc)
{
    extern __shared__ char smem[];                // NSTAGE * 64KB
    const int tid = threadIdx.x;
    const int b = tid >> 5;
    const int lane = tid & 31;
    const int c = blockIdx.x;
    const int s0 = c * CHUNK;
    const int s1 = min(s0 + CHUNK, S_LEN);
    const int nIter = s1 - s0;

    // prologue: fill the pipe
#pragma unroll
    for (int k = 0; k < NSTAGE; k++) {
        if (k < nIter)
            issue_stage(smem + k * STAGE_BYTES,
                        enc + (size_t)(s0 + k) * (BATCH * H2DIM), tid);
        asm volatile("cp.async.commit_group;");
    }

    // my slice of altered_state[b,:]
    float alt[32];
    {
        const float4* ap = (const float4*)(g_altered + b * H2DIM);
#pragma unroll
        for (int k = 0; k < 8; k++) {
            float4 v = __ldg(ap + lane + 32 * k);
            alt[4 * k + 0] = v.x; alt[4 * k + 1] = v.y;
            alt[4 * k + 2] = v.z; alt[4 * k + 3] = v.w;
        }
    }

    float acc[32];
#pragma unroll
    for (int j = 0; j < 32; j++) acc[j] = 0.f;
    float m = -1e30f, l = 0.f;

    for (int i = 0; i < nIter; i++) {
        asm volatile("cp.async.wait_group %0;" :: "n"(NSTAGE - 1));
        __syncthreads();

        const float4* bp = (const float4*)(smem + (i % NSTAGE) * STAGE_BYTES
                                           + b * (H2DIM * 4));
        float4 e[8];
#pragma unroll
        for (int k = 0; k < 8; k++) e[k] = bp[lane + 32 * k];

        float w = 0.f;
#pragma unroll
        for (int k = 0; k < 8; k++) {
            w = fmaf(e[k].x, alt[4 * k + 0], w);
            w = fmaf(e[k].y, alt[4 * k + 1], w);
            w = fmaf(e[k].z, alt[4 * k + 2], w);
            w = fmaf(e[k].w, alt[4 * k + 3], w);
        }
#pragma unroll
        for (int off = 16; off > 0; off >>= 1)
            w += __shfl_xor_sync(0xffffffffu, w, off);

        if (w > m) {                    // warp-uniform
            float sc = __expf(m - w);
            m = w;
            l *= sc;
#pragma unroll
            for (int j = 0; j < 32; j++) acc[j] *= sc;
        }
        float p = __expf(w - m);
        l += p;
#pragma unroll
        for (int k = 0; k < 8; k++) {
            acc[4 * k + 0] = fmaf(p, e[k].x, acc[4 * k + 0]);
            acc[4 * k + 1] = fmaf(p, e[k].y, acc[4 * k + 1]);
            acc[4 * k + 2] = fmaf(p, e[k].z, acc[4 * k + 2]);
            acc[4 * k + 3] = fmaf(p, e[k].w, acc[4 * k + 3]);
        }
        if (lane == 0) g_wraw[b * S_LEN + s0 + i] = w;

        __syncthreads();                 // all warps done with buffer i%NSTAGE
        int nxt = i + NSTAGE;
        if (nxt < nIter)
            issue_stage(smem + (nxt % NSTAGE) * STAGE_BYTES,
                        enc + (size_t)(s0 + nxt) * (BATCH * H2DIM), tid);
        asm volatile("cp.async.commit_group;");   // keep group count aligned
    }
    asm volatile("cp.async.wait_group 0;");

    if (lane == 0) {
        g_m[c * BATCH + b] = m;
        g_l[c * BATCH + b] = l;
    }
    float4* outp = (float4*)(g_acc + ((size_t)c * BATCH + b) * H2DIM);
#pragma unroll
    for (int k = 0; k < 8; k++)
        outp[lane + 32 * k] = make_float4(acc[4 * k + 0], acc[4 * k + 1],
                                          acc[4 * k + 2], acc[4 * k + 3]);
}

// ---------------------------------------------------------------------------
// Kernel 3: finish. grid = (BATCH, 20), block = 256.
// tiles 0..3  : attention_applied dims [t*256, t*256+256)
// tiles 4..19 : normalized_weights s in [(t-4)*256, ...)
// Each block redundantly recomputes M, L from the 152 chunk stats (cheap).
// ---------------------------------------------------------------------------
__global__ void __launch_bounds__(256, 4)
k_finish(float* __restrict__ out)
{
    const int b = blockIdx.x;
    const int t = blockIdx.y;
    const int tid = threadIdx.x;
    __shared__ float sM, sInvL;
    __shared__ float s_coef[NCHUNK];

    if (tid < 32) {
        float mx = -1e30f;
        for (int c2 = tid; c2 < NCHUNK; c2 += 32)
            mx = fmaxf(mx, g_m[c2 * BATCH + b]);
#pragma unroll
        for (int off = 16; off > 0; off >>= 1)
            mx = fmaxf(mx, __shfl_xor_sync(0xffffffffu, mx, off));
        float ls = 0.f;
        for (int c2 = tid; c2 < NCHUNK; c2 += 32)
            ls += __expf(g_m[c2 * BATCH + b] - mx) * g_l[c2 * BATCH + b];
#pragma unroll
        for (int off = 16; off > 0; off >>= 1)
            ls += __shfl_xor_sync(0xffffffffu, ls, off);
        if (tid == 0) { sM = mx; sInvL = 1.f / ls; }
    }
    __syncthreads();
    const float M = sM, invL = sInvL;

    if (t < 4) {
        for (int c2 = tid; c2 < NCHUNK; c2 += 256)
            s_coef[c2] = __expf(g_m[c2 * BATCH + b] - M);
        __syncthreads();
        const int d = t * 256 + tid;
        float a = 0.f;
#pragma unroll 4
        for (int c2 = 0; c2 < NCHUNK; c2++)
            a = fmaf(s_coef[c2], g_acc[((size_t)c2 * BATCH + b) * H2DIM + d], a);
        out[b * H2DIM + d] = a * invL;
    } else {
        const int s = (t - 4) * 256 + tid;
        out[BATCH * H2DIM + b * S_LEN + s] =
            __expf(g_wraw[b * S_LEN + s] - M) * invL;
    }
}

// ---------------------------------------------------------------------------
extern "C" void kernel_launch(void* const* d_in, const int* in_sizes, int n_in,
                              void* d_out, int out_size)
{
    const float* enc    = (const float*)d_in[0];
    const float* state  = (const float*)d_in[1];
    const float* attn_w = (const float*)d_in[3];
    const float* attn_b = (const float*)d_in[4];
    float* out = (float*)d_out;

    static int attr_done = 0;
    if (!attr_done) {
        cudaFuncSetAttribute(k_altered,
            cudaFuncAttributeMaxDynamicSharedMemorySize, BATCH * H2DIM * 4);
        cudaFuncSetAttribute(k_mainpass,
            cudaFuncAttributeMaxDynamicSharedMemorySize, NSTAGE * STAGE_BYTES);
        attr_done = 1;
    }

    k_altered<<<NCHUNK, 512, BATCH * H2DIM * 4>>>(state, attn_w, attn_b);
    k_mainpass<<<NCHUNK, 512, NSTAGE * STAGE_BYTES>>>(enc);
    k_finish<<<dim3(BATCH, 20), 256>>>(out);
}

// round 3
// speedup vs baseline: 1.0677x; 1.0317x over previous
#include <cuda_runtime.h>
#include <math.h>

#define S_LEN 4096
#define BATCH 16
#define H2DIM 1024
#define NCHUNK 152
#define CHUNK ((S_LEN + NCHUNK - 1) / NCHUNK)   // 27
#define ROW_BYTES (BATCH * H2DIM * 4)           // 64KB per s-row
#define SLICE_BYTES (H2DIM * 4)                 // 4KB per (s, b) slice
#define NSTAGE 3

// Scratch (allocation-free contract)
__device__ float g_altered[BATCH * H2DIM];
__device__ float g_wraw[BATCH * S_LEN];
__device__ float g_m[NCHUNK * BATCH];
__device__ float g_l[NCHUNK * BATCH];
__device__ float g_acc[(size_t)NCHUNK * BATCH * H2DIM];

// ---- packed f32x2 helpers (sm_10x FFMA2 path) ------------------------------
__device__ __forceinline__ unsigned long long fma2(unsigned long long a,
                                                   unsigned long long b,
                                                   unsigned long long c) {
    unsigned long long d;
    asm("fma.rn.f32x2 %0, %1, %2, %3;" : "=l"(d) : "l"(a), "l"(b), "l"(c));
    return d;
}
__device__ __forceinline__ unsigned long long mul2(unsigned long long a,
                                                   unsigned long long b) {
    unsigned long long d;
    asm("mul.rn.f32x2 %0, %1, %2;" : "=l"(d) : "l"(a), "l"(b));
    return d;
}
__device__ __forceinline__ unsigned long long pk2(float lo, float hi) {
    unsigned long long r;
    asm("mov.b64 %0, {%1, %2};" : "=l"(r) : "f"(lo), "f"(hi));
    return r;
}
__device__ __forceinline__ float2 upk2(unsigned long long v) {
    float2 r;
    asm("mov.b64 {%0, %1}, %2;" : "=f"(r.x), "=f"(r.y) : "l"(v));
    return r;
}

// ---------------------------------------------------------------------------
// Kernel 1: altered_state = state @ attn_w^T + attn_b
// grid=256, block=256 (8 warps). Block owns 4 rows; each row handled by 2
// warps (8 batches each). 2048 warps total -> latency fully hidden.
// ---------------------------------------------------------------------------
__global__ void __launch_bounds__(256, 2)
k_altered(const float* __restrict__ state,
          const float* __restrict__ attn_w,
          const float* __restrict__ attn_b)
{
    const int tid = threadIdx.x;
    const int wid = tid >> 5, lane = tid & 31;
    const int r = blockIdx.x * 4 + (wid >> 1);
    const int bg = (wid & 1) * 8;                 // batch group: 0 or 8

    const float4* wr = (const float4*)(attn_w + (size_t)r * H2DIM);
    ulonglong2 wv[8];
#pragma unroll
    for (int k = 0; k < 8; k++) {
        float4 v = __ldg(wr + lane + 32 * k);
        wv[k] = *(ulonglong2*)&v;
    }
    const float bias = __ldg(attn_b + r);

    float res[8];
#pragma unroll
    for (int bb = 0; bb < 8; bb++) {
        const float4* sp = (const float4*)(state + (size_t)(bg + bb) * H2DIM);
        unsigned long long a2 = 0ull;             // (0.f, 0.f)
#pragma unroll
        for (int k = 0; k < 8; k++) {
            float4 s = __ldg(sp + lane + 32 * k);
            ulonglong2 s2 = *(ulonglong2*)&s;
            a2 = fma2(wv[k].x, s2.x, a2);
            a2 = fma2(wv[k].y, s2.y, a2);
        }
        float2 f = upk2(a2);
        float p = f.x + f.y;
#pragma unroll
        for (int off = 16; off > 0; off >>= 1)
            p += __shfl_xor_sync(0xffffffffu, p, off);
        res[bb] = p + bias;
    }
    if (lane == 0) {
#pragma unroll
        for (int bb = 0; bb < 8; bb++)
            g_altered[(size_t)(bg + bb) * H2DIM + r] = res[bb];
    }
}

// ---------------------------------------------------------------------------
// Kernel 2: single-pass online softmax. grid=152, block=512.
// Warp b owns batch b with a PRIVATE cp.async ring (3 stages x 4KB slice).
// No __syncthreads in the mainloop; packed f32x2 FMA throughout.
// ---------------------------------------------------------------------------
__device__ __forceinline__ void issue_slice(unsigned sdst, const char* gsrc, int lane)
{
    unsigned sa = sdst + lane * 16;
    const char* g = gsrc + lane * 16;
#pragma unroll
    for (int r = 0; r < 8; r++) {
        asm volatile("cp.async.cg.shared.global [%0], [%1], 16;\n"
                     :: "r"(sa + r * 512), "l"(g + r * 512));
    }
    asm volatile("cp.async.commit_group;");
}

__global__ void __launch_bounds__(512, 1)
k_mainpass(const float* __restrict__ enc)
{
    extern __shared__ char smem[];                // NSTAGE * 64KB
    const int tid = threadIdx.x;
    const int b = tid >> 5;
    const int lane = tid & 31;
    const int c = blockIdx.x;
    const int s0 = c * CHUNK;
    const int s1 = min(s0 + CHUNK, S_LEN);
    const int n = s1 - s0;

    const unsigned smem_u = (unsigned)__cvta_generic_to_shared(smem);
    const unsigned slice0 = smem_u + b * SLICE_BYTES;
    const char* gbase = (const char*)enc + (size_t)b * SLICE_BYTES;

    // per-warp prologue: fill the private pipe
#pragma unroll
    for (int k = 0; k < NSTAGE; k++) {
        if (k < n)
            issue_slice(slice0 + k * ROW_BYTES,
                        gbase + (size_t)(s0 + k) * ROW_BYTES, lane);
        else
            asm volatile("cp.async.commit_group;");
    }

    // my slice of altered_state[b,:] as packed pairs
    unsigned long long alt2[16];
    {
        const float4* ap = (const float4*)(g_altered + b * H2DIM);
#pragma unroll
        for (int k = 0; k < 8; k++) {
            float4 v = __ldg(ap + lane + 32 * k);
            ulonglong2 t = *(ulonglong2*)&v;
            alt2[2 * k] = t.x;
            alt2[2 * k + 1] = t.y;
        }
    }

    unsigned long long acc2[16];
#pragma unroll
    for (int j = 0; j < 16; j++) acc2[j] = 0ull;
    float m = -1e30f, l = 0.f;

    int st = 0;
    for (int i = 0; i < n; i++) {
        asm volatile("cp.async.wait_group %0;" :: "n"(NSTAGE - 1));

        const ulonglong2* bp = (const ulonglong2*)(smem + st * ROW_BYTES
                                                   + b * SLICE_BYTES);
        ulonglong2 e2[8];
#pragma unroll
        for (int k = 0; k < 8; k++) e2[k] = bp[lane + 32 * k];

        unsigned long long w2 = 0ull;
#pragma unroll
        for (int k = 0; k < 8; k++) {
            w2 = fma2(e2[k].x, alt2[2 * k], w2);
            w2 = fma2(e2[k].y, alt2[2 * k + 1], w2);
        }
        float2 wp = upk2(w2);
        float w = wp.x + wp.y;
#pragma unroll
        for (int off = 16; off > 0; off >>= 1)
            w += __shfl_xor_sync(0xffffffffu, w, off);

        if (w > m) {                               // warp-uniform
            float sc = __expf(m - w);
            m = w;
            l *= sc;
            unsigned long long sc2 = pk2(sc, sc);
#pragma unroll
            for (int j = 0; j < 16; j++) acc2[j] = mul2(acc2[j], sc2);
        }
        float p = __expf(w - m);
        l += p;
        unsigned long long p2 = pk2(p, p);
#pragma unroll
        for (int k = 0; k < 8; k++) {
            acc2[2 * k]     = fma2(p2, e2[k].x, acc2[2 * k]);
            acc2[2 * k + 1] = fma2(p2, e2[k].y, acc2[2 * k + 1]);
        }
        if (lane == 0) g_wraw[b * S_LEN + s0 + i] = w;

        int nxt = i + NSTAGE;
        if (nxt < n)
            issue_slice(slice0 + st * ROW_BYTES,     // buffer st is now free
                        gbase + (size_t)(s0 + nxt) * ROW_BYTES, lane);
        else
            asm volatile("cp.async.commit_group;");
        st = (st == NSTAGE - 1) ? 0 : st + 1;
    }
    asm volatile("cp.async.wait_group 0;");

    if (lane == 0) {
        g_m[c * BATCH + b] = m;
        g_l[c * BATCH + b] = l;
    }
    float4* outp = (float4*)(g_acc + ((size_t)c * BATCH + b) * H2DIM);
#pragma unroll
    for (int k = 0; k < 8; k++) {
        float2 a = upk2(acc2[2 * k]);
        float2 bq = upk2(acc2[2 * k + 1]);
        outp[lane + 32 * k] = make_float4(a.x, a.y, bq.x, bq.y);
    }
}

// ---------------------------------------------------------------------------
// Kernel 3: finish. grid = (BATCH, 20), block = 256.
// tiles 0..3: attention_applied; tiles 4..19: normalized_weights.
// ---------------------------------------------------------------------------
__global__ void __launch_bounds__(256, 4)
k_finish(float* __restrict__ out)
{
    const int b = blockIdx.x;
    const int t = blockIdx.y;
    const int tid = threadIdx.x;
    __shared__ float sM, sInvL;
    __shared__ float s_coef[NCHUNK];

    if (tid < 32) {
        float mx = -1e30f;
        for (int c2 = tid; c2 < NCHUNK; c2 += 32)
            mx = fmaxf(mx, g_m[c2 * BATCH + b]);
#pragma unroll
        for (int off = 16; off > 0; off >>= 1)
            mx = fmaxf(mx, __shfl_xor_sync(0xffffffffu, mx, off));
        float ls = 0.f;
        for (int c2 = tid; c2 < NCHUNK; c2 += 32)
            ls += __expf(g_m[c2 * BATCH + b] - mx) * g_l[c2 * BATCH + b];
#pragma unroll
        for (int off = 16; off > 0; off >>= 1)
            ls += __shfl_xor_sync(0xffffffffu, ls, off);
        if (tid == 0) { sM = mx; sInvL = 1.f / ls; }
    }
    __syncthreads();
    const float M = sM, invL = sInvL;

    if (t < 4) {
        for (int c2 = tid; c2 < NCHUNK; c2 += 256)
            s_coef[c2] = __expf(g_m[c2 * BATCH + b] - M);
        __syncthreads();
        const int d = t * 256 + tid;
        float a = 0.f;
#pragma unroll 4
        for (int c2 = 0; c2 < NCHUNK; c2++)
            a = fmaf(s_coef[c2], g_acc[((size_t)c2 * BATCH + b) * H2DIM + d], a);
        out[b * H2DIM + d] = a * invL;
    } else {
        const int s = (t - 4) * 256 + tid;
        out[BATCH * H2DIM + b * S_LEN + s] =
            __expf(g_wraw[b * S_LEN + s] - M) * invL;
    }
}

// ---------------------------------------------------------------------------
extern "C" void kernel_launch(void* const* d_in, const int* in_sizes, int n_in,
                              void* d_out, int out_size)
{
    const float* enc    = (const float*)d_in[0];
    const float* state  = (const float*)d_in[1];
    const float* attn_w = (const float*)d_in[3];
    const float* attn_b = (const float*)d_in[4];
    float* out = (float*)d_out;

    static int attr_done = 0;
    if (!attr_done) {
        cudaFuncSetAttribute(k_mainpass,
            cudaFuncAttributeMaxDynamicSharedMemorySize, NSTAGE * ROW_BYTES);
        attr_done = 1;
    }

    k_altered<<<256, 256>>>(state, attn_w, attn_b);
    k_mainpass<<<NCHUNK, 512, NSTAGE * ROW_BYTES>>>(enc);
    k_finish<<<dim3(BATCH, 20), 256>>>(out);
}

// round 4
// speedup vs baseline: 1.2051x; 1.1287x over previous
#include <cuda_runtime.h>
#include <math.h>

#define S_LEN 4096
#define BATCH 16
#define H2DIM 1024
#define NCHUNK 152
#define CHUNK ((S_LEN + NCHUNK - 1) / NCHUNK)   // 27
#define ROW_BYTES (BATCH * H2DIM * 4)           // 64KB per s-row
#define SLICE_BYTES (H2DIM * 4)                 // 4KB per (s,b) slice
#define NSTAGE 3
#define MBAR_OFF (NSTAGE * ROW_BYTES)           // mbar area after 192KB
#define MAIN_SMEM (MBAR_OFF + 16 * NSTAGE * 8)

// Scratch (allocation-free contract)
__device__ float g_altered[BATCH * H2DIM];
__device__ float g_wraw[BATCH * S_LEN];
__device__ float g_m[NCHUNK * BATCH];
__device__ float g_l[NCHUNK * BATCH];
__device__ float g_acc[(size_t)NCHUNK * BATCH * H2DIM];

// ---- packed f32x2 helpers ---------------------------------------------------
__device__ __forceinline__ unsigned long long fma2(unsigned long long a,
                                                   unsigned long long b,
                                                   unsigned long long c) {
    unsigned long long d;
    asm("fma.rn.f32x2 %0, %1, %2, %3;" : "=l"(d) : "l"(a), "l"(b), "l"(c));
    return d;
}
__device__ __forceinline__ unsigned long long mul2(unsigned long long a,
                                                   unsigned long long b) {
    unsigned long long d;
    asm("mul.rn.f32x2 %0, %1, %2;" : "=l"(d) : "l"(a), "l"(b));
    return d;
}
__device__ __forceinline__ unsigned long long pk2(float lo, float hi) {
    unsigned long long r;
    asm("mov.b64 %0, {%1, %2};" : "=l"(r) : "f"(lo), "f"(hi));
    return r;
}
__device__ __forceinline__ float2 upk2(unsigned long long v) {
    float2 r;
    asm("mov.b64 {%0, %1}, %2;" : "=f"(r.x), "=f"(r.y) : "l"(v));
    return r;
}

// ---------------------------------------------------------------------------
// Kernel 1: altered = state @ attn_w^T + attn_b
// grid=64, block=256 (8 warps). state staged ONCE per block into smem (L2
// traffic 64 blocks * 64KB = 4MB). Warp handles 2 rows x all 16 batches.
// ---------------------------------------------------------------------------
__global__ void __launch_bounds__(256, 1)
k_altered(const float* __restrict__ state,
          const float* __restrict__ attn_w,
          const float* __restrict__ attn_b)
{
    extern __shared__ float s_state[];            // 64KB
    const int tid = threadIdx.x;
    const int wid = tid >> 5, lane = tid & 31;

    float4* sv = (float4*)s_state;
    const float4* gs = (const float4*)state;
#pragma unroll
    for (int k = 0; k < 16; k++)
        sv[tid + 256 * k] = __ldg(gs + tid + 256 * k);
    __syncthreads();

    const int r0 = blockIdx.x * 16 + wid * 2;
    const int r1 = r0 + 1;

    ulonglong2 w0[8], w1[8];
    const float4* wr0 = (const float4*)(attn_w + (size_t)r0 * H2DIM);
    const float4* wr1 = (const float4*)(attn_w + (size_t)r1 * H2DIM);
#pragma unroll
    for (int k = 0; k < 8; k++) {
        float4 a = __ldg(wr0 + lane + 32 * k);
        float4 b = __ldg(wr1 + lane + 32 * k);
        w0[k] = *(ulonglong2*)&a;
        w1[k] = *(ulonglong2*)&b;
    }
    const float bias0 = __ldg(attn_b + r0);
    const float bias1 = __ldg(attn_b + r1);

#pragma unroll 2
    for (int b = 0; b < BATCH; b++) {
        const float4* sp = (const float4*)(s_state + b * H2DIM);
        unsigned long long a0 = 0ull, a1 = 0ull;
#pragma unroll
        for (int k = 0; k < 8; k++) {
            float4 s = sp[lane + 32 * k];
            ulonglong2 s2 = *(ulonglong2*)&s;
            a0 = fma2(w0[k].x, s2.x, a0);
            a0 = fma2(w0[k].y, s2.y, a0);
            a1 = fma2(w1[k].x, s2.x, a1);
            a1 = fma2(w1[k].y, s2.y, a1);
        }
        float2 f0 = upk2(a0), f1 = upk2(a1);
        float p0 = f0.x + f0.y, p1 = f1.x + f1.y;
#pragma unroll
        for (int off = 16; off > 0; off >>= 1) {
            p0 += __shfl_xor_sync(0xffffffffu, p0, off);
            p1 += __shfl_xor_sync(0xffffffffu, p1, off);
        }
        if (lane == 0) {
            g_altered[b * H2DIM + r0] = p0 + bias0;
            g_altered[b * H2DIM + r1] = p1 + bias1;
        }
    }
}

// ---------------------------------------------------------------------------
// Kernel 2: single-pass online softmax, per-warp TMA bulk pipeline (3 slots).
// grid=152, block=512, warp b owns batch b. Slot re-issued right after its
// LDS drain, moving memory issue off the serial softmax chain.
// ---------------------------------------------------------------------------
__global__ void __launch_bounds__(512, 1)
k_mainpass(const float* __restrict__ enc)
{
    extern __shared__ char smem[];
    const int tid = threadIdx.x;
    const int b = tid >> 5;
    const int lane = tid & 31;
    const int c = blockIdx.x;
    const int s0 = c * CHUNK;
    const int s1 = min(s0 + CHUNK, S_LEN);
    const int n = s1 - s0;

    const unsigned smem_u = (unsigned)__cvta_generic_to_shared(smem);
    const unsigned slice0 = smem_u + b * SLICE_BYTES;
    const unsigned mbar0 = smem_u + MBAR_OFF + b * (NSTAGE * 8);
    const char* gbase = (const char*)enc + (size_t)b * SLICE_BYTES;

    if (lane == 0) {
#pragma unroll
        for (int k = 0; k < NSTAGE; k++)
            asm volatile("mbarrier.init.shared.b64 [%0], 1;"
                         :: "r"(mbar0 + k * 8) : "memory");
        asm volatile("fence.proxy.async.shared::cta;" ::: "memory");
        // prologue: fill 3 slots (n >= 19 always)
#pragma unroll
        for (int k = 0; k < NSTAGE; k++) {
            unsigned mb = mbar0 + k * 8;
            asm volatile("mbarrier.arrive.expect_tx.shared.b64 _, [%0], %1;"
                         :: "r"(mb), "r"(SLICE_BYTES) : "memory");
            asm volatile(
                "cp.async.bulk.shared::cluster.global.mbarrier::complete_tx::bytes "
                "[%0], [%1], %2, [%3];"
                :: "r"(slice0 + k * ROW_BYTES),
                   "l"(gbase + (size_t)(s0 + k) * ROW_BYTES),
                   "r"(SLICE_BYTES), "r"(mb) : "memory");
        }
    }

    // my slice of altered_state[b,:] (overlaps with TMA)
    unsigned long long alt2[16];
    {
        const float4* ap = (const float4*)(g_altered + b * H2DIM);
#pragma unroll
        for (int k = 0; k < 8; k++) {
            float4 v = __ldg(ap + lane + 32 * k);
            ulonglong2 t = *(ulonglong2*)&v;
            alt2[2 * k] = t.x;
            alt2[2 * k + 1] = t.y;
        }
    }

    unsigned long long acc2[16];
#pragma unroll
    for (int j = 0; j < 16; j++) acc2[j] = 0ull;
    float m = -1e30f, l = 0.f;

    int slot = 0, par = 0;
    for (int i = 0; i < n; i++) {
        const unsigned mb = mbar0 + slot * 8;
        // wait for slot (all lanes)
        unsigned done;
        asm volatile(
            "{\n\t.reg .pred p;\n\t"
            "mbarrier.try_wait.parity.acquire.cta.shared::cta.b64 p, [%1], %2;\n\t"
            "selp.b32 %0, 1, 0, p;\n\t}"
            : "=r"(done) : "r"(mb), "r"(par) : "memory");
        if (!done) {
            asm volatile(
                "{\n\t.reg .pred P1;\n\t"
                "W0_%=:\n\t"
                "mbarrier.try_wait.parity.acquire.cta.shared::cta.b64 P1, [%0], %1, 0x989680;\n\t"
                "@P1 bra.uni W1_%=;\n\t"
                "bra.uni W0_%=;\n\t"
                "W1_%=:\n\t}"
                :: "r"(mb), "r"(par) : "memory");
        }

        const ulonglong2* bp = (const ulonglong2*)(smem + slot * ROW_BYTES
                                                   + b * SLICE_BYTES);
        ulonglong2 e2[8];
#pragma unroll
        for (int k = 0; k < 8; k++) e2[k] = bp[lane + 32 * k];

        // slot drained into registers -> re-issue immediately (lane 0)
        int nxt = i + NSTAGE;
        if (nxt < n && lane == 0) {
            asm volatile("mbarrier.arrive.expect_tx.shared.b64 _, [%0], %1;"
                         :: "r"(mb), "r"(SLICE_BYTES) : "memory");
            asm volatile(
                "cp.async.bulk.shared::cluster.global.mbarrier::complete_tx::bytes "
                "[%0], [%1], %2, [%3];"
                :: "r"(slice0 + slot * ROW_BYTES),
                   "l"(gbase + (size_t)(s0 + nxt) * ROW_BYTES),
                   "r"(SLICE_BYTES), "r"(mb) : "memory");
        }

        unsigned long long w2 = 0ull;
#pragma unroll
        for (int k = 0; k < 8; k++) {
            w2 = fma2(e2[k].x, alt2[2 * k], w2);
            w2 = fma2(e2[k].y, alt2[2 * k + 1], w2);
        }
        float2 wp = upk2(w2);
        float w = wp.x + wp.y;
#pragma unroll
        for (int off = 16; off > 0; off >>= 1)
            w += __shfl_xor_sync(0xffffffffu, w, off);

        if (w > m) {                               // warp-uniform
            float sc = __expf(m - w);
            m = w;
            l *= sc;
            unsigned long long sc2 = pk2(sc, sc);
#pragma unroll
            for (int j = 0; j < 16; j++) acc2[j] = mul2(acc2[j], sc2);
        }
        float p = __expf(w - m);
        l += p;
        unsigned long long p2 = pk2(p, p);
#pragma unroll
        for (int k = 0; k < 8; k++) {
            acc2[2 * k]     = fma2(p2, e2[k].x, acc2[2 * k]);
            acc2[2 * k + 1] = fma2(p2, e2[k].y, acc2[2 * k + 1]);
        }
        if (lane == 0) g_wraw[b * S_LEN + s0 + i] = w;

        if (++slot == NSTAGE) { slot = 0; par ^= 1; }
    }

    if (lane == 0) {
        g_m[c * BATCH + b] = m;
        g_l[c * BATCH + b] = l;
    }
    float4* outp = (float4*)(g_acc + ((size_t)c * BATCH + b) * H2DIM);
#pragma unroll
    for (int k = 0; k < 8; k++) {
        float2 a = upk2(acc2[2 * k]);
        float2 bq = upk2(acc2[2 * k + 1]);
        outp[lane + 32 * k] = make_float4(a.x, a.y, bq.x, bq.y);
    }
}

// ---------------------------------------------------------------------------
// Kernel 3: finish. grid = (BATCH, 24), block 512.
// t in [0,16): attention_applied d-tile of 64, 8 parallel c2-groups (19 each).
// t in [16,24): normalized_weights s-tile of 512.
// ---------------------------------------------------------------------------
__global__ void __launch_bounds__(512, 2)
k_finish(float* __restrict__ out)
{
    const int b = blockIdx.x;
    const int t = blockIdx.y;
    const int tid = threadIdx.x;
    __shared__ float sM, sInvL;
    __shared__ float s_coef[NCHUNK];
    __shared__ float s_part[512];

    if (tid < 32) {
        float mx = -1e30f;
        for (int c2 = tid; c2 < NCHUNK; c2 += 32)
            mx = fmaxf(mx, g_m[c2 * BATCH + b]);
#pragma unroll
        for (int off = 16; off > 0; off >>= 1)
            mx = fmaxf(mx, __shfl_xor_sync(0xffffffffu, mx, off));
        float ls = 0.f;
        for (int c2 = tid; c2 < NCHUNK; c2 += 32)
            ls += __expf(g_m[c2 * BATCH + b] - mx) * g_l[c2 * BATCH + b];
#pragma unroll
        for (int off = 16; off > 0; off >>= 1)
            ls += __shfl_xor_sync(0xffffffffu, ls, off);
        if (tid == 0) { sM = mx; sInvL = 1.f / ls; }
    }
    __syncthreads();
    const float M = sM, invL = sInvL;

    if (t < 16) {
        if (tid < NCHUNK) s_coef[tid] = __expf(g_m[tid * BATCH + b] - M);
        __syncthreads();
        const int doff = tid & 63;
        const int g = tid >> 6;                 // 0..7
        const int d = t * 64 + doff;
        float a = 0.f;
#pragma unroll
        for (int k = 0; k < 19; k++) {          // 152 = 8 * 19
            int c2 = g + 8 * k;
            a = fmaf(s_coef[c2], g_acc[((size_t)c2 * BATCH + b) * H2DIM + d], a);
        }
        s_part[tid] = a;
        __syncthreads();
        if (tid < 64) {
            float v = 0.f;
#pragma unroll
            for (int gg = 0; gg < 8; gg++) v += s_part[gg * 64 + tid];
            out[b * H2DIM + d] = v * invL;
        }
    } else {
        const int s = (t - 16) * 512 + tid;
        out[BATCH * H2DIM + b * S_LEN + s] =
            __expf(g_wraw[b * S_LEN + s] - M) * invL;
    }
}

// ---------------------------------------------------------------------------
extern "C" void kernel_launch(void* const* d_in, const int* in_sizes, int n_in,
                              void* d_out, int out_size)
{
    const float* enc    = (const float*)d_in[0];
    const float* state  = (const float*)d_in[1];
    const float* attn_w = (const float*)d_in[3];
    const float* attn_b = (const float*)d_in[4];
    float* out = (float*)d_out;

    static int attr_done = 0;
    if (!attr_done) {
        cudaFuncSetAttribute(k_altered,
            cudaFuncAttributeMaxDynamicSharedMemorySize, BATCH * H2DIM * 4);
        cudaFuncSetAttribute(k_mainpass,
            cudaFuncAttributeMaxDynamicSharedMemorySize, MAIN_SMEM);
        attr_done = 1;
    }

    k_altered<<<64, 256, BATCH * H2DIM * 4>>>(state, attn_w, attn_b);
    k_mainpass<<<NCHUNK, 512, MAIN_SMEM>>>(enc);
    k_finish<<<dim3(BATCH, 24), 512>>>(out);
}